// round 7
// baseline (speedup 1.0000x reference)
#include <cuda_runtime.h>
#include <cstdint>

// out[s,:] = W_tok[x[s],:] + b_tok + W_pos[(S-1)-s,:] + b_pos
// S=8192, D=1024 fp32.
// R6: L2 residency steering, sm_103a-legal encoding. evict_last requires
// 256-bit loads (.v8.b32) on this arch -> 32 B/thread, 2 rows per 256-thread
// iteration, 8 rows/CTA. Reads pinned (evict_last), output streamed (.cs).

constexpr int SEQ   = 8192;
constexpr int EMBED = 1024;
constexpr int ROWS  = 8;                  // rows per CTA
constexpr int ITERS = ROWS / 2;           // 2 rows per 256-thread iteration

__device__ __forceinline__ void ld_pin8(const float* p, float* v) {
    uint32_t r0, r1, r2, r3, r4, r5, r6, r7;
    asm volatile(
        "ld.global.nc.L2::evict_last.v8.b32 {%0,%1,%2,%3,%4,%5,%6,%7}, [%8];"
        : "=r"(r0), "=r"(r1), "=r"(r2), "=r"(r3),
          "=r"(r4), "=r"(r5), "=r"(r6), "=r"(r7)
        : "l"(p));
    v[0] = __uint_as_float(r0); v[1] = __uint_as_float(r1);
    v[2] = __uint_as_float(r2); v[3] = __uint_as_float(r3);
    v[4] = __uint_as_float(r4); v[5] = __uint_as_float(r5);
    v[6] = __uint_as_float(r6); v[7] = __uint_as_float(r7);
}

__device__ __forceinline__ void st_stream4(float* p, float a, float b, float c, float d) {
    asm volatile("st.global.cs.v4.f32 [%0], {%1,%2,%3,%4};"
                 :: "l"(p), "f"(a), "f"(b), "f"(c), "f"(d) : "memory");
}

__global__ __launch_bounds__(256)
void linear_embedding_kernel(const int* __restrict__ x,
                             const float* __restrict__ W_tok,
                             const float* __restrict__ b_tok,
                             const float* __restrict__ W_pos,
                             const float* __restrict__ b_pos,
                             float* __restrict__ out)
{
    const int t   = threadIdx.x;
    const int sub = t >> 7;        // row within the 2-row group (0/1)
    const int c   = (t & 127) * 8; // float offset of this thread's 32B chunk
    const int s0  = blockIdx.x * ROWS;

    // Front-batch token ids (broadcast loads).
    int tok[ROWS];
#pragma unroll
    for (int i = 0; i < ROWS; ++i)
        tok[i] = __ldg(&x[s0 + i]);

    // Bias chunk for this thread's columns (zeros in practice, L2-resident).
    float b[8];
#pragma unroll
    for (int k = 0; k < 8; ++k)
        b[k] = __ldg(&b_tok[c + k]) + __ldg(&b_pos[c + k]);

#pragma unroll
    for (int j = 0; j < ITERS; ++j) {
        const int i   = j * 2 + sub;       // row index within CTA
        const int s   = s0 + i;            // global row
        const int pos = SEQ - 1 - s;

        float a[8], p[8];
        ld_pin8(W_tok + (long long)tok[i] * EMBED + c, a);
        ld_pin8(W_pos + (long long)pos    * EMBED + c, p);

        float r[8];
#pragma unroll
        for (int k = 0; k < 8; ++k)
            r[k] = (a[k] + p[k]) + b[k];

        float* o = out + (long long)s * EMBED + c;
        st_stream4(o,     r[0], r[1], r[2], r[3]);
        st_stream4(o + 4, r[4], r[5], r[6], r[7]);
    }
}

extern "C" void kernel_launch(void* const* d_in, const int* in_sizes, int n_in,
                              void* d_out, int out_size)
{
    const int*   x     = (const int*)d_in[0];
    const float* W_tok = (const float*)d_in[1];
    const float* b_tok = (const float*)d_in[2];
    const float* W_pos = (const float*)d_in[3];
    const float* b_pos = (const float*)d_in[4];
    float* out = (float*)d_out;

    linear_embedding_kernel<<<SEQ / ROWS, 256>>>(x, W_tok, b_tok, W_pos, b_pos, out);
}

// round 8
// speedup vs baseline: 1.4775x; 1.4775x over previous
#include <cuda_runtime.h>

// out[s,:] = W_tok[x[s],:] + b_tok + W_pos[(S-1)-s,:] + b_pos
// S=8192, D=1024 fp32.
// R7: single-wave persistent kernel + software pipeline. All prior profiles
// show NOTHING saturated (DRAM<=54%, L2 33%, issue<=21%) => structure-bound.
// Multi-wave launches re-pay the x->gather dependent chain and wave-transition
// cost 6x. One resident wave, grid-stride, prefetch tokens 2 ahead / rows 1
// ahead: chain paid once, then pure streaming.

constexpr int SEQ   = 8192;
constexpr int EMBED = 1024;
constexpr int VEC   = EMBED / 4;   // 256 float4 per row
constexpr int GRID  = 888;         // 148 SMs x 6 CTAs -> exactly one wave

__global__ __launch_bounds__(256, 6)
void linear_embedding_kernel(const int* __restrict__ x,
                             const float4* __restrict__ W_tok,
                             const float4* __restrict__ b_tok,
                             const float4* __restrict__ W_pos,
                             const float4* __restrict__ b_pos,
                             float4* __restrict__ out)
{
    const int t      = threadIdx.x;
    const int stride = GRID;

    // Bias for this thread's column (zeros in practice; L2-resident).
    const float4 bt = __ldg(&b_tok[t]);
    const float4 bp = __ldg(&b_pos[t]);
    float4 b;
    b.x = bt.x + bp.x; b.y = bt.y + bp.y;
    b.z = bt.z + bp.z; b.w = bt.w + bp.w;

    int s = blockIdx.x;

    // Pipeline prologue: token ids 2 stages ahead, rows 1 stage ahead.
    int s1 = min(s + stride, SEQ - 1);
    int tok0 = __ldg(&x[s]);
    int tok1 = __ldg(&x[s1]);

    float4 a0 = __ldg(&W_tok[(long long)tok0 * VEC + t]);
    float4 p0 = __ldg(&W_pos[(long long)(SEQ - 1 - s) * VEC + t]);

    while (s < SEQ) {
        const int s_next = s + stride;

        // Prefetch next row's data (clamped; harmless duplicate on tail).
        const int sn = min(s_next, SEQ - 1);
        float4 a1 = __ldg(&W_tok[(long long)tok1 * VEC + t]);
        float4 p1 = __ldg(&W_pos[(long long)(SEQ - 1 - sn) * VEC + t]);
        // Prefetch token id 2 stages ahead.
        const int s2 = min(s_next + stride, SEQ - 1);
        const int tok2 = __ldg(&x[s2]);

        // Consume current row.
        float4 r;
        r.x = (a0.x + p0.x) + b.x;
        r.y = (a0.y + p0.y) + b.y;
        r.z = (a0.z + p0.z) + b.z;
        r.w = (a0.w + p0.w) + b.w;
        out[(long long)s * VEC + t] = r;

        // Rotate pipeline.
        s = s_next;
        a0 = a1; p0 = p1;
        tok1 = tok2;
    }
}

extern "C" void kernel_launch(void* const* d_in, const int* in_sizes, int n_in,
                              void* d_out, int out_size)
{
    const int*    x     = (const int*)d_in[0];
    const float4* W_tok = (const float4*)d_in[1];
    const float4* b_tok = (const float4*)d_in[2];
    const float4* W_pos = (const float4*)d_in[3];
    const float4* b_pos = (const float4*)d_in[4];
    float4* out = (float4*)d_out;

    linear_embedding_kernel<<<GRID, 256>>>(x, W_tok, b_tok, W_pos, b_pos, out);
}